// round 16
// baseline (speedup 1.0000x reference)
#include <cuda_runtime.h>
#include <cuda_fp16.h>
#include <cstdint>

// GCN 2-layer: out = spmm(relu(spmm(X)@W1))@W2,  A_norm = D^-1/2 A D^-1/2
// N=50000, E=850000 (last N edges self-loops, runtime-verified), D=64.
//
// R16 = R14/R15 design (64-row-CTA HMMA gemm) with the forced
// __launch_bounds__ min-blocks removed: R14/R15 both hit container failures
// and the (128,8) bound (63.5K/64K regs) is the only aggressive delta vs the
// proven R13. Natural occupancy at ~62 regs/16.5KB smem is already ~8 CTAs/SM.
// Scatter untouched: measured REDG-lane-rate floor (~36us each).

#define D 64
#define NMAX 50176

__device__ __half g_xs[NMAX * D];   // prescaled features fp16 (xs, then hs)
__device__ float  g_agg[NMAX * D];  // layer-1 aggregation (fp32)
__device__ float  g_agg2[NMAX * D]; // layer-2 aggregation (fp32)
__device__ int g_is64;
__device__ int g_loops;
__device__ int g_E2;

// ---------------------------------------------------------------------------
// helpers
// ---------------------------------------------------------------------------
__device__ __forceinline__ unsigned h2u(float a, float b) {
    __half2 h = __floats2half2_rn(a, b);
    union { __half2 h; unsigned u; } c;
    c.h = h;
    return c.u;
}
__device__ __forceinline__ __half2 u2h(unsigned u) {
    union { unsigned u; __half2 h; } c;
    c.u = u;
    return c.h;
}
__device__ __forceinline__ void ldmatrix_x4(unsigned* r, unsigned addr) {
    asm volatile("ldmatrix.sync.aligned.m8n8.x4.shared.b16 {%0,%1,%2,%3}, [%4];"
                 : "=r"(r[0]), "=r"(r[1]), "=r"(r[2]), "=r"(r[3]) : "r"(addr));
}
__device__ __forceinline__ void ldmatrix_x4_t(unsigned* r, unsigned addr) {
    asm volatile("ldmatrix.sync.aligned.m8n8.x4.trans.shared.b16 {%0,%1,%2,%3}, [%4];"
                 : "=r"(r[0]), "=r"(r[1]), "=r"(r[2]), "=r"(r[3]) : "r"(addr));
}
__device__ __forceinline__ void mma16816(float* c, const unsigned* a,
                                         unsigned b0, unsigned b1) {
    asm volatile(
        "mma.sync.aligned.m16n8k16.row.col.f32.f16.f16.f32 "
        "{%0,%1,%2,%3}, {%4,%5,%6,%7}, {%8,%9}, {%0,%1,%2,%3};"
        : "+f"(c[0]), "+f"(c[1]), "+f"(c[2]), "+f"(c[3])
        : "r"(a[0]), "r"(a[1]), "r"(a[2]), "r"(a[3]), "r"(b0), "r"(b1));
}

// ---------------------------------------------------------------------------
// Detection: edge dtype + trailing-self-loop structure.
// ---------------------------------------------------------------------------
__global__ void __launch_bounds__(1024) detect_kernel(const void* __restrict__ ei,
                                                      int E, int N) {
    __shared__ int s_is64;
    __shared__ int s_ok;
    int t = threadIdx.x;
    if (t == 0) {
        const int* w = (const int*)ei;
        int is64 = 1;
        #pragma unroll 1
        for (int i = 0; i < 64; i++)
            if (w[2 * i + 1] != 0) { is64 = 0; break; }
        s_is64 = is64;
        s_ok = (E >= N) ? 1 : 0;
    }
    __syncthreads();
    int is64 = s_is64;
    if (E >= N) {
        long long pos = (long long)t * N / 1024;
        long long eidx = (long long)(E - N) + pos;
        long long s, d;
        if (is64) {
            const long long* p = (const long long*)ei;
            s = p[eidx]; d = p[E + eidx];
        } else {
            const int* p = (const int*)ei;
            s = p[eidx]; d = p[E + eidx];
        }
        if (s != pos || d != pos) s_ok = 0;
    }
    __syncthreads();
    if (t == 0) {
        g_is64 = is64;
        g_loops = s_ok;
        g_E2 = s_ok ? (E - N) : E;
    }
}

// ---------------------------------------------------------------------------
// Fused prescale + layer1 init:
//   xs16[i,:] = (half)(dis[i] * x[i,:]) ;  agg1[i,:] = loops ? dis*x : 0 (fp32)
// ---------------------------------------------------------------------------
__global__ void __launch_bounds__(256) prescale_kernel(
    const float4* __restrict__ x, const float* __restrict__ dis,
    uint4* __restrict__ xs, float4* __restrict__ agg, int n8)
{
    int i = blockIdx.x * 256 + threadIdx.x;
    if (i >= n8) return;
    float s = dis[i >> 3];
    float4 a = x[i * 2];
    float4 b = x[i * 2 + 1];
    a.x *= s; a.y *= s; a.z *= s; a.w *= s;
    b.x *= s; b.y *= s; b.z *= s; b.w *= s;
    uint4 o;
    o.x = h2u(a.x, a.y); o.y = h2u(a.z, a.w);
    o.z = h2u(b.x, b.y); o.w = h2u(b.z, b.w);
    xs[i] = o;
    if (g_loops) {
        agg[i * 2]     = a;
        agg[i * 2 + 1] = b;
    } else {
        float4 z = make_float4(0.f, 0.f, 0.f, 0.f);
        agg[i * 2]     = z;
        agg[i * 2 + 1] = z;
    }
}

// ---------------------------------------------------------------------------
// Scatter SPMM: out[dst] += (float)feat16[src]
// 16 threads/edge; each LDG.64 (4 halves), one red.global.add.v4.f32.
// ---------------------------------------------------------------------------
__global__ void __launch_bounds__(256) scatter_kernel(
    const uint2* __restrict__ feat,
    const void*  __restrict__ ei,
    float*       __restrict__ out,
    int E)
{
    int idx = blockIdx.x * 256 + threadIdx.x;
    int e = idx >> 4;
    if (e >= g_E2) return;
    int lane = idx & 15;

    int s, d;
    if (g_is64) {
        const long long* p = (const long long*)ei;
        s = (int)p[e];
        d = (int)p[E + e];
    } else {
        const int* p = (const int*)ei;
        s = p[e];
        d = p[E + e];
    }

    uint2 v = feat[s * 16 + lane];
    float2 f0 = __half22float2(u2h(v.x));
    float2 f1 = __half22float2(u2h(v.y));

    float* o = out + d * 64 + lane * 4;
    asm volatile("red.global.add.v4.f32 [%0], {%1, %2, %3, %4};"
                 :: "l"(o), "f"(f0.x), "f"(f0.y), "f"(f1.x), "f"(f1.y)
                 : "memory");
}

// ---------------------------------------------------------------------------
// Tensor-core GEMM: t = dis[r] * (X[r,:] @ W),  W 64x64, X fp32 in gmem.
//   mode 0: Yf = t (fp32)
//   mode 1: h = relu(t)*dis[r]; Yh = (half)h; A2 = (loops ? h : 0) (fp32)
// 128 thr (4 warps x 16 rows = 64 rows/CTA), grid = ceil(N/64) = 782.
// fp16 smem staging (128B-row XOR swizzle) + ldmatrix + mma.m16n8k16.
// ---------------------------------------------------------------------------
__global__ void __launch_bounds__(128) gemm64_kernel(
    const float* __restrict__ X,
    const float* __restrict__ W,
    const float* __restrict__ dis,
    float*       __restrict__ Yf,
    __half*      __restrict__ Yh,
    float*       __restrict__ A2,
    int n, int mode)
{
    __shared__ __align__(16) __half Wh[64 * 64];    // [k][n], 128B rows
    __shared__ __align__(16) __half Xh[64 * 64];    // [row][k], 128B rows

    int t = threadIdx.x;
    int rbase = blockIdx.x * 64;

    // ---- stage W (fp32 -> fp16, swizzled): 128 thr, each 64B of one row ----
    {
        int row = t >> 1, q2 = t & 1;               // row 0..63, half 0..1
        const float4* W4 = (const float4*)W;
        unsigned sw = (row & 7) << 4;
        char* base = (char*)Wh;
        #pragma unroll
        for (int c = 0; c < 4; c++) {
            float4 fa = W4[row * 16 + q2 * 8 + c * 2 + 0];
            float4 fb = W4[row * 16 + q2 * 8 + c * 2 + 1];
            uint4 u;
            u.x = h2u(fa.x, fa.y); u.y = h2u(fa.z, fa.w);
            u.z = h2u(fb.x, fb.y); u.w = h2u(fb.z, fb.w);
            *(uint4*)(base + ((row * 128 + (q2 * 4 + c) * 16) ^ sw)) = u;
        }
    }

    // ---- stage X tile (fp32 -> fp16, swizzled): rows 0..63 ----
    {
        int row = t >> 1, h = t & 1;
        int gr = rbase + row;
        const float4* X4 = (const float4*)X;
        unsigned sw = (row & 7) << 4;
        char* base = (char*)Xh;
        #pragma unroll
        for (int c = 0; c < 4; c++) {
            float4 fa, fb;
            if (gr < n) {
                fa = X4[gr * 16 + h * 8 + c * 2 + 0];
                fb = X4[gr * 16 + h * 8 + c * 2 + 1];
            } else {
                fa = make_float4(0.f, 0.f, 0.f, 0.f);
                fb = fa;
            }
            uint4 u;
            u.x = h2u(fa.x, fa.y); u.y = h2u(fa.z, fa.w);
            u.z = h2u(fb.x, fb.y); u.w = h2u(fb.z, fb.w);
            *(uint4*)(base + ((row * 128 + (h * 4 + c) * 16) ^ sw)) = u;
        }
    }
    __syncthreads();

    int lane = t & 31, wid = t >> 5;
    int r0 = wid << 4;                              // warp rows: wid*16..+15

    unsigned xbase = (unsigned)__cvta_generic_to_shared(Xh);
    unsigned wbase = (unsigned)__cvta_generic_to_shared(Wh);

    // ---- A fragments ----
    unsigned a[4][4];
    {
        int row = r0 + (lane & 7) + (lane & 8);
        unsigned sw = (row & 7) << 4;
        #pragma unroll
        for (int kk = 0; kk < 4; kk++) {
            int chunk = kk * 2 + (lane >> 4);
            unsigned addr = xbase + ((row * 128 + chunk * 16) ^ sw);
            ldmatrix_x4(a[kk], addr);
        }
    }

    float c[8][4];
    #pragma unroll
    for (int j = 0; j < 8; j++)
        #pragma unroll
        for (int q = 0; q < 4; q++)
            c[j][q] = 0.f;

    #pragma unroll
    for (int j = 0; j < 8; j++) {
        unsigned b[8];
        {
            int k0 = lane;
            unsigned addr0 = wbase + ((k0 * 128 + j * 16) ^ ((k0 & 7) << 4));
            ldmatrix_x4_t(b + 0, addr0);
            int k1 = 32 + lane;
            unsigned addr1 = wbase + ((k1 * 128 + j * 16) ^ ((k1 & 7) << 4));
            ldmatrix_x4_t(b + 4, addr1);
        }
        mma16816(c[j], a[0], b[0], b[1]);
        mma16816(c[j], a[1], b[2], b[3]);
        mma16816(c[j], a[2], b[4], b[5]);
        mma16816(c[j], a[3], b[6], b[7]);
    }

    // ---- epilogue ----
    int loops = (mode == 1) ? g_loops : 0;
    int rA = rbase + r0 + (lane >> 2);
    int rB = rA + 8;
    int cb = (lane & 3) << 1;
    float sA = (rA < n) ? dis[rA] : 0.f;
    float sB = (rB < n) ? dis[rB] : 0.f;

    #pragma unroll
    for (int j = 0; j < 8; j++) {
        int col = j * 8 + cb;
        if (mode == 0) {
            if (rA < n)
                *(float2*)&Yf[rA * 64 + col] = make_float2(c[j][0] * sA, c[j][1] * sA);
            if (rB < n)
                *(float2*)&Yf[rB * 64 + col] = make_float2(c[j][2] * sB, c[j][3] * sB);
        } else {
            if (rA < n) {
                float h0 = fmaxf(c[j][0] * sA, 0.f) * sA;
                float h1 = fmaxf(c[j][1] * sA, 0.f) * sA;
                *(__half2*)&Yh[rA * 64 + col] = __floats2half2_rn(h0, h1);
                *(float2*)&A2[rA * 64 + col] =
                    loops ? make_float2(h0, h1) : make_float2(0.f, 0.f);
            }
            if (rB < n) {
                float h2 = fmaxf(c[j][2] * sB, 0.f) * sB;
                float h3 = fmaxf(c[j][3] * sB, 0.f) * sB;
                *(__half2*)&Yh[rB * 64 + col] = __floats2half2_rn(h2, h3);
                *(float2*)&A2[rB * 64 + col] =
                    loops ? make_float2(h2, h3) : make_float2(0.f, 0.f);
            }
        }
    }
}

// ---------------------------------------------------------------------------
// Launch
// ---------------------------------------------------------------------------
extern "C" void kernel_launch(void* const* d_in, const int* in_sizes, int n_in,
                              void* d_out, int out_size)
{
    const float* x   = (const float*)d_in[0];
    const void*  ei  = d_in[1];
    const float* dis = (const float*)d_in[2];
    const float* W1  = (const float*)d_in[n_in - 2];
    const float* W2  = (const float*)d_in[n_in - 1];

    int N = in_sizes[0] / D;
    int E = in_sizes[1] / 2;

    __half* xs  = nullptr;
    float* agg  = nullptr;
    float* agg2 = nullptr;
    cudaGetSymbolAddress((void**)&xs,   g_xs);
    cudaGetSymbolAddress((void**)&agg,  g_agg);
    cudaGetSymbolAddress((void**)&agg2, g_agg2);

    int n8    = N * (D / 8);
    int pgrid = (n8 + 255) / 256;
    int sgrid = (E * 16 + 255) / 256;
    int mgrid = (N + 63) / 64;

    detect_kernel<<<1, 1024>>>(ei, E, N);

    // Layer 1
    prescale_kernel<<<pgrid, 256>>>((const float4*)x, dis,
                                    (uint4*)xs, (float4*)agg, n8);
    scatter_kernel<<<sgrid, 256>>>((const uint2*)xs, ei, agg, E);
    gemm64_kernel<<<mgrid, 128>>>(agg, W1, dis, nullptr, xs, agg2, N, 1); // xs := hs16

    // Layer 2
    scatter_kernel<<<sgrid, 256>>>((const uint2*)xs, ei, agg2, E);
    gemm64_kernel<<<mgrid, 128>>>(agg2, W2, dis, (float*)d_out, nullptr, nullptr, N, 0);
}

// round 17
// speedup vs baseline: 1.0512x; 1.0512x over previous
#include <cuda_runtime.h>
#include <cuda_fp16.h>
#include <cstdint>

// GCN 2-layer: out = spmm(relu(spmm(X)@W1))@W2,  A_norm = D^-1/2 A D^-1/2
// N=50000, E=850000 (last N edges self-loops, runtime-verified), D=64.
//
// R17: warp-split-N HMMA gemm. R16 taught that total warps (N/16=3125) was
// the occupancy cap, not CTA shape. Now each warp owns 16 rows x 32 cols ->
// 6250 warps (~42/SM), 64 rows/CTA, 256 thr (4 row-groups x 2 col-halves).
// Warp-level fragment code identical to validated R13 with halved j-range.
// Scatter untouched: measured REDG-lane-rate floor (~36us each).

#define D 64
#define NMAX 50176

__device__ __half g_xs[NMAX * D];   // prescaled features fp16 (xs, then hs)
__device__ float  g_agg[NMAX * D];  // layer-1 aggregation (fp32)
__device__ float  g_agg2[NMAX * D]; // layer-2 aggregation (fp32)
__device__ int g_is64;
__device__ int g_loops;
__device__ int g_E2;

// ---------------------------------------------------------------------------
// helpers
// ---------------------------------------------------------------------------
__device__ __forceinline__ unsigned h2u(float a, float b) {
    __half2 h = __floats2half2_rn(a, b);
    union { __half2 h; unsigned u; } c;
    c.h = h;
    return c.u;
}
__device__ __forceinline__ __half2 u2h(unsigned u) {
    union { unsigned u; __half2 h; } c;
    c.u = u;
    return c.h;
}
__device__ __forceinline__ void ldmatrix_x4(unsigned* r, unsigned addr) {
    asm volatile("ldmatrix.sync.aligned.m8n8.x4.shared.b16 {%0,%1,%2,%3}, [%4];"
                 : "=r"(r[0]), "=r"(r[1]), "=r"(r[2]), "=r"(r[3]) : "r"(addr));
}
__device__ __forceinline__ void ldmatrix_x4_t(unsigned* r, unsigned addr) {
    asm volatile("ldmatrix.sync.aligned.m8n8.x4.trans.shared.b16 {%0,%1,%2,%3}, [%4];"
                 : "=r"(r[0]), "=r"(r[1]), "=r"(r[2]), "=r"(r[3]) : "r"(addr));
}
__device__ __forceinline__ void mma16816(float* c, const unsigned* a,
                                         unsigned b0, unsigned b1) {
    asm volatile(
        "mma.sync.aligned.m16n8k16.row.col.f32.f16.f16.f32 "
        "{%0,%1,%2,%3}, {%4,%5,%6,%7}, {%8,%9}, {%0,%1,%2,%3};"
        : "+f"(c[0]), "+f"(c[1]), "+f"(c[2]), "+f"(c[3])
        : "r"(a[0]), "r"(a[1]), "r"(a[2]), "r"(a[3]), "r"(b0), "r"(b1));
}

// ---------------------------------------------------------------------------
// Detection: edge dtype + trailing-self-loop structure.
// ---------------------------------------------------------------------------
__global__ void __launch_bounds__(1024) detect_kernel(const void* __restrict__ ei,
                                                      int E, int N) {
    __shared__ int s_is64;
    __shared__ int s_ok;
    int t = threadIdx.x;
    if (t == 0) {
        const int* w = (const int*)ei;
        int is64 = 1;
        #pragma unroll 1
        for (int i = 0; i < 64; i++)
            if (w[2 * i + 1] != 0) { is64 = 0; break; }
        s_is64 = is64;
        s_ok = (E >= N) ? 1 : 0;
    }
    __syncthreads();
    int is64 = s_is64;
    if (E >= N) {
        long long pos = (long long)t * N / 1024;
        long long eidx = (long long)(E - N) + pos;
        long long s, d;
        if (is64) {
            const long long* p = (const long long*)ei;
            s = p[eidx]; d = p[E + eidx];
        } else {
            const int* p = (const int*)ei;
            s = p[eidx]; d = p[E + eidx];
        }
        if (s != pos || d != pos) s_ok = 0;
    }
    __syncthreads();
    if (t == 0) {
        g_is64 = is64;
        g_loops = s_ok;
        g_E2 = s_ok ? (E - N) : E;
    }
}

// ---------------------------------------------------------------------------
// Fused prescale + layer1 init:
//   xs16[i,:] = (half)(dis[i] * x[i,:]) ;  agg1[i,:] = loops ? dis*x : 0 (fp32)
// ---------------------------------------------------------------------------
__global__ void __launch_bounds__(256) prescale_kernel(
    const float4* __restrict__ x, const float* __restrict__ dis,
    uint4* __restrict__ xs, float4* __restrict__ agg, int n8)
{
    int i = blockIdx.x * 256 + threadIdx.x;
    if (i >= n8) return;
    float s = dis[i >> 3];
    float4 a = x[i * 2];
    float4 b = x[i * 2 + 1];
    a.x *= s; a.y *= s; a.z *= s; a.w *= s;
    b.x *= s; b.y *= s; b.z *= s; b.w *= s;
    uint4 o;
    o.x = h2u(a.x, a.y); o.y = h2u(a.z, a.w);
    o.z = h2u(b.x, b.y); o.w = h2u(b.z, b.w);
    xs[i] = o;
    if (g_loops) {
        agg[i * 2]     = a;
        agg[i * 2 + 1] = b;
    } else {
        float4 z = make_float4(0.f, 0.f, 0.f, 0.f);
        agg[i * 2]     = z;
        agg[i * 2 + 1] = z;
    }
}

// ---------------------------------------------------------------------------
// Scatter SPMM: out[dst] += (float)feat16[src]
// 16 threads/edge; each LDG.64 (4 halves), one red.global.add.v4.f32.
// ---------------------------------------------------------------------------
__global__ void __launch_bounds__(256) scatter_kernel(
    const uint2* __restrict__ feat,
    const void*  __restrict__ ei,
    float*       __restrict__ out,
    int E)
{
    int idx = blockIdx.x * 256 + threadIdx.x;
    int e = idx >> 4;
    if (e >= g_E2) return;
    int lane = idx & 15;

    int s, d;
    if (g_is64) {
        const long long* p = (const long long*)ei;
        s = (int)p[e];
        d = (int)p[E + e];
    } else {
        const int* p = (const int*)ei;
        s = p[e];
        d = p[E + e];
    }

    uint2 v = feat[s * 16 + lane];
    float2 f0 = __half22float2(u2h(v.x));
    float2 f1 = __half22float2(u2h(v.y));

    float* o = out + d * 64 + lane * 4;
    asm volatile("red.global.add.v4.f32 [%0], {%1, %2, %3, %4};"
                 :: "l"(o), "f"(f0.x), "f"(f0.y), "f"(f1.x), "f"(f1.y)
                 : "memory");
}

// ---------------------------------------------------------------------------
// Tensor-core GEMM (warp-split-N): t = dis[r] * (X[r,:] @ W),  W 64x64.
//   mode 0: Yf = t (fp32)
//   mode 1: h = relu(t)*dis[r]; Yh = (half)h; A2 = (loops ? h : 0) (fp32)
// 256 thr, 64 rows/CTA. 8 warps = 4 row-groups x 2 col-halves; each warp
// does 16 rows x 32 cols (4 n-tiles). grid = ceil(N/64) = 782 -> 6250 warps.
// ---------------------------------------------------------------------------
__global__ void __launch_bounds__(256) gemm64_kernel(
    const float* __restrict__ X,
    const float* __restrict__ W,
    const float* __restrict__ dis,
    float*       __restrict__ Yf,
    __half*      __restrict__ Yh,
    float*       __restrict__ A2,
    int n, int mode)
{
    __shared__ __align__(16) __half Wh[64 * 64];    // [k][n], 128B rows
    __shared__ __align__(16) __half Xh[64 * 64];    // [row][k], 128B rows

    int t = threadIdx.x;
    int rbase = blockIdx.x * 64;

    // ---- stage W: 256 thr, each 32B of one row (row = t>>2, quarter = t&3) ----
    {
        int row = t >> 2, q = t & 3;
        const float4* W4 = (const float4*)W;
        unsigned sw = (row & 7) << 4;
        char* base = (char*)Wh;
        #pragma unroll
        for (int c = 0; c < 2; c++) {
            float4 fa = W4[row * 16 + q * 4 + c * 2 + 0];
            float4 fb = W4[row * 16 + q * 4 + c * 2 + 1];
            uint4 u;
            u.x = h2u(fa.x, fa.y); u.y = h2u(fa.z, fa.w);
            u.z = h2u(fb.x, fb.y); u.w = h2u(fb.z, fb.w);
            *(uint4*)(base + ((row * 128 + (q * 2 + c) * 16) ^ sw)) = u;
        }
    }

    // ---- stage X tile: rows 0..63, each thread 32B ----
    {
        int row = t >> 2, q = t & 3;
        int gr = rbase + row;
        const float4* X4 = (const float4*)X;
        unsigned sw = (row & 7) << 4;
        char* base = (char*)Xh;
        #pragma unroll
        for (int c = 0; c < 2; c++) {
            float4 fa, fb;
            if (gr < n) {
                fa = X4[gr * 16 + q * 4 + c * 2 + 0];
                fb = X4[gr * 16 + q * 4 + c * 2 + 1];
            } else {
                fa = make_float4(0.f, 0.f, 0.f, 0.f);
                fb = fa;
            }
            uint4 u;
            u.x = h2u(fa.x, fa.y); u.y = h2u(fa.z, fa.w);
            u.z = h2u(fb.x, fb.y); u.w = h2u(fb.z, fb.w);
            *(uint4*)(base + ((row * 128 + (q * 2 + c) * 16) ^ sw)) = u;
        }
    }
    __syncthreads();

    int lane = t & 31, wid = t >> 5;
    int r0 = (wid >> 1) << 4;                       // row-group: 0,16,32,48
    int jbase = (wid & 1) << 2;                     // n-tiles 0..3 or 4..7

    unsigned xbase = (unsigned)__cvta_generic_to_shared(Xh);
    unsigned wbase = (unsigned)__cvta_generic_to_shared(Wh);

    // ---- A fragments (16 rows x 64 k) ----
    unsigned a[4][4];
    {
        int row = r0 + (lane & 7) + (lane & 8);
        unsigned sw = (row & 7) << 4;
        #pragma unroll
        for (int kk = 0; kk < 4; kk++) {
            int chunk = kk * 2 + (lane >> 4);
            unsigned addr = xbase + ((row * 128 + chunk * 16) ^ sw);
            ldmatrix_x4(a[kk], addr);
        }
    }

    float c[4][4];
    #pragma unroll
    for (int j = 0; j < 4; j++)
        #pragma unroll
        for (int q = 0; q < 4; q++)
            c[j][q] = 0.f;

    // ---- MMA: this warp's 4 n-tiles ----
    #pragma unroll
    for (int jj = 0; jj < 4; jj++) {
        int j = jbase + jj;
        unsigned b[8];
        {
            int k0 = lane;
            unsigned addr0 = wbase + ((k0 * 128 + j * 16) ^ ((k0 & 7) << 4));
            ldmatrix_x4_t(b + 0, addr0);
            int k1 = 32 + lane;
            unsigned addr1 = wbase + ((k1 * 128 + j * 16) ^ ((k1 & 7) << 4));
            ldmatrix_x4_t(b + 4, addr1);
        }
        mma16816(c[jj], a[0], b[0], b[1]);
        mma16816(c[jj], a[1], b[2], b[3]);
        mma16816(c[jj], a[2], b[4], b[5]);
        mma16816(c[jj], a[3], b[6], b[7]);
    }

    // ---- epilogue ----
    int loops = (mode == 1) ? g_loops : 0;
    int rA = rbase + r0 + (lane >> 2);
    int rB = rA + 8;
    int cb = (lane & 3) << 1;
    float sA = (rA < n) ? dis[rA] : 0.f;
    float sB = (rB < n) ? dis[rB] : 0.f;

    #pragma unroll
    for (int jj = 0; jj < 4; jj++) {
        int col = (jbase + jj) * 8 + cb;
        if (mode == 0) {
            if (rA < n)
                *(float2*)&Yf[rA * 64 + col] = make_float2(c[jj][0] * sA, c[jj][1] * sA);
            if (rB < n)
                *(float2*)&Yf[rB * 64 + col] = make_float2(c[jj][2] * sB, c[jj][3] * sB);
        } else {
            if (rA < n) {
                float h0 = fmaxf(c[jj][0] * sA, 0.f) * sA;
                float h1 = fmaxf(c[jj][1] * sA, 0.f) * sA;
                *(__half2*)&Yh[rA * 64 + col] = __floats2half2_rn(h0, h1);
                *(float2*)&A2[rA * 64 + col] =
                    loops ? make_float2(h0, h1) : make_float2(0.f, 0.f);
            }
            if (rB < n) {
                float h2 = fmaxf(c[jj][2] * sB, 0.f) * sB;
                float h3 = fmaxf(c[jj][3] * sB, 0.f) * sB;
                *(__half2*)&Yh[rB * 64 + col] = __floats2half2_rn(h2, h3);
                *(float2*)&A2[rB * 64 + col] =
                    loops ? make_float2(h2, h3) : make_float2(0.f, 0.f);
            }
        }
    }
}

// ---------------------------------------------------------------------------
// Launch
// ---------------------------------------------------------------------------
extern "C" void kernel_launch(void* const* d_in, const int* in_sizes, int n_in,
                              void* d_out, int out_size)
{
    const float* x   = (const float*)d_in[0];
    const void*  ei  = d_in[1];
    const float* dis = (const float*)d_in[2];
    const float* W1  = (const float*)d_in[n_in - 2];
    const float* W2  = (const float*)d_in[n_in - 1];

    int N = in_sizes[0] / D;
    int E = in_sizes[1] / 2;

    __half* xs  = nullptr;
    float* agg  = nullptr;
    float* agg2 = nullptr;
    cudaGetSymbolAddress((void**)&xs,   g_xs);
    cudaGetSymbolAddress((void**)&agg,  g_agg);
    cudaGetSymbolAddress((void**)&agg2, g_agg2);

    int n8    = N * (D / 8);
    int pgrid = (n8 + 255) / 256;
    int sgrid = (E * 16 + 255) / 256;
    int mgrid = (N + 63) / 64;

    detect_kernel<<<1, 1024>>>(ei, E, N);

    // Layer 1
    prescale_kernel<<<pgrid, 256>>>((const float4*)x, dis,
                                    (uint4*)xs, (float4*)agg, n8);
    scatter_kernel<<<sgrid, 256>>>((const uint2*)xs, ei, agg, E);
    gemm64_kernel<<<mgrid, 256>>>(agg, W1, dis, nullptr, xs, agg2, N, 1); // xs := hs16

    // Layer 2
    scatter_kernel<<<sgrid, 256>>>((const uint2*)xs, ei, agg2, E);
    gemm64_kernel<<<mgrid, 256>>>(agg2, W2, dis, (float*)d_out, nullptr, nullptr, N, 0);
}